// round 15
// baseline (speedup 1.0000x reference)
#include <cuda_runtime.h>
#include <cuda_bf16.h>
#include <cstdint>

// ---------------- static scratch ----------------
__device__ int g_node_off[1025];

__global__ void k_prefix(const int* __restrict__ bn, int B) {
    if (threadIdx.x == 0) {
        int acc = 0;
        g_node_off[0] = 0;
        for (int i = 0; i < B; ++i) { acc += bn[i]; g_node_off[i + 1] = acc; }
    }
}

// ---------------- fast path: bulk-async staged accumulation ------------------
// CTA = (graph, chunk); 4 warps; warp w owns columns [32w, 32w+32).
// A 32-node batch is 16KB CONTIGUOUS in gmem -> one cp.async.bulk per batch
// (issued by tid 0) into a 4-stage smem ring with mbarrier complete_tx.
// Load concurrency costs no registers and no warp issue slots: up to 3
// stages (48KB) in flight per CTA, 2 CTAs/SM.
// Numerics (plan/rmw split, leader/donor merge) = R12's validated code; only
// the stage addressing changed to full 512B rows.
#define FULLM 0xffffffffu
#define NSTAGES 4
#define STAGE_FLOATS 4096              // 16KB per stage

struct Meta { int seg; float inv; };
struct Plan { unsigned sp0, sp1, pmask, cmask; };

__device__ __forceinline__ void mbar_init(unsigned mbar, unsigned count) {
    asm volatile("mbarrier.init.shared.b64 [%0], %1;" :: "r"(mbar), "r"(count) : "memory");
}
__device__ __forceinline__ void mbar_expect_tx(unsigned mbar, unsigned bytes) {
    asm volatile("mbarrier.arrive.expect_tx.shared.b64 _, [%0], %1;"
                 :: "r"(mbar), "r"(bytes) : "memory");
}
__device__ __forceinline__ void bulk_g2s(unsigned dst_smem, const void* gsrc,
                                         unsigned bytes, unsigned mbar) {
    asm volatile(
        "cp.async.bulk.shared::cta.global.mbarrier::complete_tx::bytes "
        "[%0], [%1], %2, [%3];"
        :: "r"(dst_smem), "l"(gsrc), "r"(bytes), "r"(mbar) : "memory");
}
__device__ __forceinline__ void mbar_wait(unsigned mbar, unsigned parity) {
    asm volatile(
        "{\n\t"
        ".reg .pred P1;\n\t"
        "WAIT_LOOP_%=:\n\t"
        "mbarrier.try_wait.parity.acquire.cta.shared::cta.b64 P1, [%0], %1, 0x989680;\n\t"
        "@P1 bra.uni WAIT_DONE_%=;\n\t"
        "bra.uni WAIT_LOOP_%=;\n\t"
        "WAIT_DONE_%=:\n\t"
        "}"
        :: "r"(mbar), "r"(parity) : "memory");
}

__device__ __forceinline__ Meta load_xy(
    const int* __restrict__ xy, int base, int cend, int G, int lane)
{
    Meta m;
    const int cnt = cend - base;                   // >= 1
    const int l   = (lane < cnt) ? lane : (cnt - 1);
    const int nd  = base + l;
    const int rr  = __ldg(&xy[3 * nd + 0]);
    const int cc  = __ldg(&xy[3 * nd + 1]);
    const int dv  = __ldg(&xy[3 * nd + 2]);
    m.seg = (lane < cnt) ? (rr * G + cc) : (64 + lane);   // marker never matches
    m.inv = 1.0f / (float)dv;
    return m;
}

__device__ __forceinline__ void plan_batch(
    Plan& P, float invs[8], const Meta& m,
    int base, int cend, int lane, int grp, unsigned below)
{
    const int cnt = (cend - base >= 32) ? 32 : (cend - base);
    unsigned pm = 0, s0 = 0, s1 = 0, cm = 0;

    #pragma unroll
    for (int it = 0; it < 8; ++it) {
        const int      nb     = it * 4 + grp;
        const int      seg    = __shfl_sync(FULLM, m.seg, nb);
        invs[it]              = __shfl_sync(FULLM, m.inv, nb);
        const unsigned mm     = __match_any_sync(FULLM, seg);
        const bool     leader = (mm & below) == 0u;
        const bool     act    = (nb < cnt);

        const unsigned sb = (unsigned)(seg & 63) << ((it & 3) * 8);
        if (it < 4) s0 |= sb; else s1 |= sb;
        if (act && leader) pm |= (1u << it);

        if (!__all_sync(FULLM, leader)) {              // warp-uniform
            pm |= (1u << (8 + it));
            const unsigned c1 = ((grp < 3) && ((mm >> ((lane + 8)  & 31)) & 1u)) ? 1u : 0u;
            const unsigned c2 = ((grp < 2) && ((mm >> ((lane + 16) & 31)) & 1u)) ? 2u : 0u;
            const unsigned c3 = ((grp < 1) && ((mm >> ((lane + 24) & 31)) & 1u)) ? 4u : 0u;
            cm |= (c1 | c2 | c3) << (it * 3);
        }
    }
    P.sp0 = s0; P.sp1 = s1; P.pmask = pm; P.cmask = cm;
}

// stage holds 32 full rows of 128 floats; warp w reads cols [32w, 32w+32)
__device__ __forceinline__ void rmw_batch(
    float* __restrict__ acc, const float* __restrict__ stage,
    const Plan& P, const float invs[8], int w, int lane, int grp, int slot)
{
    #pragma unroll
    for (int it = 0; it < 8; ++it) {
        const unsigned sp  = (it < 4) ? P.sp0 : P.sp1;
        const int      seg = (sp >> ((it & 3) * 8)) & 0x3F;
        const bool lead = (P.pmask >> it) & 1u;
        const bool rare = (P.pmask >> (8 + it)) & 1u;    // warp-uniform
        const float inv = invs[it];

        const float4 v = *reinterpret_cast<const float4*>(
            stage + (it * 4 + grp) * 128 + w * 32 + slot * 4);
        float4* ap = reinterpret_cast<float4*>(acc + seg * 32 + slot * 4);

        if (!rare) {                                     // ~91%
            if (lead) {
                float4 a = *ap;
                a.x = fmaf(v.x, inv, a.x);
                a.y = fmaf(v.y, inv, a.y);
                a.z = fmaf(v.z, inv, a.z);
                a.w = fmaf(v.w, inv, a.w);
                *ap = a;
            }
        } else {                                         // donor merge
            float wx = v.x * inv, wy = v.y * inv, wz = v.z * inv, ww = v.w * inv;
            const float x1 = __shfl_down_sync(FULLM, wx, 8);
            const float y1 = __shfl_down_sync(FULLM, wy, 8);
            const float z1 = __shfl_down_sync(FULLM, wz, 8);
            const float w1 = __shfl_down_sync(FULLM, ww, 8);
            const float x2 = __shfl_down_sync(FULLM, wx, 16);
            const float y2 = __shfl_down_sync(FULLM, wy, 16);
            const float z2 = __shfl_down_sync(FULLM, wz, 16);
            const float w2 = __shfl_down_sync(FULLM, ww, 16);
            const float x3 = __shfl_down_sync(FULLM, wx, 24);
            const float y3 = __shfl_down_sync(FULLM, wy, 24);
            const float z3 = __shfl_down_sync(FULLM, wz, 24);
            const float w3 = __shfl_down_sync(FULLM, ww, 24);
            const unsigned cf = (P.cmask >> (it * 3)) & 7u;
            const bool c1 = cf & 1u, c2 = cf & 2u, c3 = cf & 4u;
            if (lead) {
                float4 a = *ap;
                a.x += wx + (c1 ? x1 : 0.f) + (c2 ? x2 : 0.f) + (c3 ? x3 : 0.f);
                a.y += wy + (c1 ? y1 : 0.f) + (c2 ? y2 : 0.f) + (c3 ? y3 : 0.f);
                a.z += wz + (c1 ? z1 : 0.f) + (c2 ? z2 : 0.f) + (c3 ? z3 : 0.f);
                a.w += ww + (c1 ? w1 : 0.f) + (c2 ? w2 : 0.f) + (c3 ? w3 : 0.f);
                *ap = a;
            }
        }
    }
}

// dynamic smem (floats):
//   [0 .. 8192)        acc: 4 warps x 64 segs x 32 cols     (32 KB)
//   [8192 .. 24576)    stages: 4 x 4096 floats (16KB each)  (64 KB)
//   bytes [98304 .. 98336)  mbarriers: 4 x u64
#define SMEM_BYTES (98304 + 64)

__global__ void __launch_bounds__(128) spp_bulk_kernel(
    const float* __restrict__ feat,
    const int*   __restrict__ xy,
    float*       __restrict__ out,
    int G, int C)
{
    extern __shared__ float smem[];

    const int t    = threadIdx.x;
    const int w    = t >> 5;
    const int lane = t & 31;
    const int grp  = lane >> 3;
    const int slot = lane & 7;
    const unsigned below = grp ? ((1u << (grp * 8)) - 1u) : 0u;

    const int g     = blockIdx.x / C;
    const int chunk = blockIdx.x % C;
    const int gbeg  = g_node_off[g];
    const int glen  = g_node_off[g + 1] - gbeg;
    const int cbeg  = gbeg + (int)((long long)glen * chunk / C);
    const int cend  = gbeg + (int)((long long)glen * (chunk + 1) / C);
    const int nb    = (cend > cbeg) ? ((cend - cbeg + 31) >> 5) : 0;

    float* acc = smem + w * 2048;
    float* stages = smem + 8192;
    const unsigned smem_u32 = (unsigned)__cvta_generic_to_shared(smem);
    const unsigned stage_u32 = smem_u32 + 32768;
    const unsigned mbar0 = smem_u32 + 98304;

    // zero accumulators + init barriers
    float4* z = reinterpret_cast<float4*>(smem);
    #pragma unroll
    for (int i = t; i < 2048; i += 128) z[i] = make_float4(0.f, 0.f, 0.f, 0.f);
    if (t == 0) {
        #pragma unroll
        for (int s = 0; s < NSTAGES; ++s) mbar_init(mbar0 + s * 8, 1);
    }
    __syncthreads();

    // prologue: issue first NSTAGES batches
    if (t == 0) {
        #pragma unroll
        for (int k = 0; k < NSTAGES; ++k) {
            if (k < nb) {
                const int base = cbeg + k * 32;
                const int cnt  = (cend - base >= 32) ? 32 : (cend - base);
                const unsigned bytes = (unsigned)cnt * 512u;
                mbar_expect_tx(mbar0 + k * 8, bytes);
                bulk_g2s(stage_u32 + k * 16384,
                         feat + (size_t)base * 128, bytes, mbar0 + k * 8);
            }
        }
    }

    if (nb > 0) {
        Meta M = load_xy(xy, cbeg, cend, G, lane);
        for (int b = 0; b < nb; ++b) {
            const int s   = b & (NSTAGES - 1);
            const unsigned ph = (unsigned)(b >> 2) & 1u;
            const int base = cbeg + b * 32;

            mbar_wait(mbar0 + s * 8, ph);

            Plan P; float invs[8];
            plan_batch(P, invs, M, base, cend, lane, grp, below);
            if (b + 1 < nb) M = load_xy(xy, base + 32, cend, G, lane);

            rmw_batch(acc, stages + s * STAGE_FLOATS, P, invs, w, lane, grp, slot);

            __syncthreads();                         // stage s fully consumed
            const int bn = b + NSTAGES;
            if (t == 0 && bn < nb) {
                const int nbase = cbeg + bn * 32;
                const int cnt   = (cend - nbase >= 32) ? 32 : (cend - nbase);
                const unsigned bytes = (unsigned)cnt * 512u;
                mbar_expect_tx(mbar0 + s * 8, bytes);
                bulk_g2s(stage_u32 + s * 16384,
                         feat + (size_t)nbase * 128, bytes, mbar0 + s * 8);
            }
        }
    }
    __syncthreads();

    // epilogue: each warp flushes its own 8KB slice via RED.v4
    float* dstw = out + (size_t)g * 64 * 128 + (size_t)w * 32;
    #pragma unroll
    for (int i = lane; i < 512; i += 32) {
        const int seg = i >> 3, q = i & 7;
        float4 a = *reinterpret_cast<float4*>(acc + seg * 32 + q * 4);
        asm volatile("red.global.add.v4.f32 [%0], {%1, %2, %3, %4};"
                     :: "l"(dstw + (size_t)seg * 128 + q * 4),
                        "f"(a.x), "f"(a.y), "f"(a.z), "f"(a.w)
                     : "memory");
    }
}

// ---------------- fallback path (round-2 kernel) ----------------
__device__ __forceinline__ int find_graph(const int* s_off, int B, int node) {
    int lo = 0, hi = B;
    while (hi - lo > 1) {
        int mid = (lo + hi) >> 1;
        if (s_off[mid] <= node) lo = mid; else hi = mid;
    }
    return lo;
}

__global__ void __launch_bounds__(256) spp_pool_fallback(
    const float* __restrict__ feat, const int* __restrict__ xy,
    float* __restrict__ out, int N, int D, int G, int B)
{
    extern __shared__ int s_off[];
    for (int i = threadIdx.x; i <= B; i += blockDim.x) s_off[i] = g_node_off[i];
    __syncthreads();

    const int lane   = threadIdx.x & 31;
    const int warp   = (blockIdx.x * blockDim.x + threadIdx.x) >> 5;
    const int nwarps = (gridDim.x * blockDim.x) >> 5;

    for (long long base = (long long)warp * 32; base < N;
         base += (long long)nwarps * 32) {
        long long mynode = base + lane;
        int nd = (mynode < N) ? (int)mynode : (N - 1);
        const int r  = __ldg(&xy[3 * nd + 0]);
        const int c  = __ldg(&xy[3 * nd + 1]);
        const int dv = __ldg(&xy[3 * nd + 2]);
        int gid = find_graph(s_off, B, nd);
        const int   myseg = (gid * G + r) * G + c;
        const float myinv = 1.0f / (float)dv;
        const int cnt = (N - base >= 32) ? 32 : (int)(N - base);

        for (int j = 0; j < cnt; ++j) {
            const int   seg = __shfl_sync(0xffffffffu, myseg, j);
            const float inv = __shfl_sync(0xffffffffu, myinv, j);
            const float* src = feat + ((size_t)(base + j)) * D;
            for (int d4 = lane; d4 * 4 < D; d4 += 32) {
                float4 v = __ldg(reinterpret_cast<const float4*>(src) + d4);
                v.x *= inv; v.y *= inv; v.z *= inv; v.w *= inv;
                float* dst = out + (size_t)seg * D + d4 * 4;
                asm volatile("red.global.add.v4.f32 [%0], {%1, %2, %3, %4};"
                             :: "l"(dst), "f"(v.x), "f"(v.y), "f"(v.z), "f"(v.w)
                             : "memory");
            }
        }
    }
}

extern "C" void kernel_launch(void* const* d_in, const int* in_sizes, int n_in,
                              void* d_out, int out_size) {
    const float* feat = (const float*)d_in[0];
    const int*   xy   = (const int*)d_in[1];
    const int*   bn   = (const int*)d_in[2];
    float*       out  = (float*)d_out;

    const int B = in_sizes[2];
    const int N = in_sizes[1] / 3;
    const int D = in_sizes[0] / N;
    const int S = out_size / D;        // B*G*G
    const int gg = S / B;
    int G = 1;
    while (G * G < gg) ++G;

    k_prefix<<<1, 32>>>(bn, B);

    // output accumulated via RED in both paths -> zero every replay
    cudaMemsetAsync(d_out, 0, (size_t)out_size * sizeof(float), 0);

    const bool fast = (D == 128) && (gg == 64) && (G == 8) &&
                      (S == B * 64) && (B <= 1024);

    if (fast) {
        static bool attr_set = false;
        if (!attr_set) {
            cudaFuncSetAttribute(spp_bulk_kernel,
                                 cudaFuncAttributeMaxDynamicSharedMemorySize,
                                 SMEM_BYTES);
            attr_set = true;
        }
        int C = (576 + B - 1) / B;     // ~576 CTAs (2/SM, ~2 waves); B=64 -> 9
        if (C < 1) C = 1;
        spp_bulk_kernel<<<B * C, 128, SMEM_BYTES>>>(feat, xy, out, G, C);
    } else {
        size_t smem = (size_t)(B + 1) * sizeof(int);
        long long batches = ((long long)N + 31) / 32;
        int blocks = (int)((batches + 7) / 8);
        if (blocks > 65535) blocks = 65535;
        spp_pool_fallback<<<blocks, 256, smem>>>(feat, xy, out, N, D, G, B);
    }
}

// round 16
// speedup vs baseline: 2.0191x; 2.0191x over previous
#include <cuda_runtime.h>
#include <cuda_bf16.h>

// ---------------- static scratch ----------------
__device__ int g_node_off[1025];

__global__ void k_prefix(const int* __restrict__ bn, int B) {
    if (threadIdx.x == 0) {
        int acc = 0;
        g_node_off[0] = 0;
        for (int i = 0; i < B; ++i) { acc += bn[i]; g_node_off[i + 1] = acc; }
    }
}

// ---------------- fast path (R9 + L2 prefetch) ------------------------------
// CTA = (graph, chunk); 4 warps, warp w owns 32-col slice [32w, 32w+32).
// Every warp walks all 32-node batches of the chunk.
// Per-warp private accumulator: 64 segs x 32 floats (stride 32, conflict-free).
// Pipeline: load(b+1) -> rmw(b) -> meta(b+1)   [R9, unchanged]
// R16: ONE added instruction per batch: each lane prefetch.global.L2's the
// 128B line of this warp's slice for one row of batch b+4. Fire-and-forget
// (no regs, no scoreboard) -> the LDG.128s hit L2 (~250cyc) instead of DRAM,
// and the prefetch stream carries unbounded MLP to DRAM.
#define FULLM 0xffffffffu

struct Batch {
    int      seg;        // this lane's node seg (64+lane marker if inactive)
    float    inv;
    float4   vv[8];      // after meta: scaled + donor-merged
    unsigned sp0, sp1;   // after meta: segs of iters 0..3 / 4..7, 8b each
    unsigned pmask;      // after meta: bit it = (active && leader)
};

__device__ __forceinline__ void prefetch_l2(const float* p) {
    asm volatile("prefetch.global.L2 [%0];" :: "l"(p));
}

// one predicated prefetch per lane: row (pfbase+lane), this warp's 128B slice
__device__ __forceinline__ void prefetch_batch(
    const float* __restrict__ fwarp, int pfbase, int cend, int lane)
{
    const int node = pfbase + lane;
    if (node < cend)
        prefetch_l2(fwarp + (size_t)node * 128);
}

__device__ __forceinline__ void load_batch(
    Batch& b, const int* __restrict__ xy, const float* __restrict__ fbase,
    int base, int cend, int G, int lane, int grp)
{
    const int cnt = cend - base;                   // >= 1 (may exceed 32)
    const int l   = (lane < cnt) ? lane : (cnt - 1);
    const int nd  = base + l;
    const int rr  = __ldg(&xy[3 * nd + 0]);
    const int cc  = __ldg(&xy[3 * nd + 1]);
    const int dv  = __ldg(&xy[3 * nd + 2]);
    b.seg = (lane < cnt) ? (rr * G + cc) : (64 + lane);  // marker never matches
    b.inv = 1.0f / (float)dv;

    #pragma unroll
    for (int it = 0; it < 8; ++it) {
        const int nb   = it * 4 + grp;
        const int node = base + ((nb < cnt) ? nb : (cnt - 1));
        b.vv[it] = __ldg(reinterpret_cast<const float4*>(fbase + (size_t)node * 128));
    }
}

__device__ __forceinline__ void meta_batch(
    Batch& b, int base, int cend, int lane, int grp, unsigned below)
{
    const int cnt = (cend - base >= 32) ? 32 : (cend - base);
    unsigned pm = 0, s0 = 0, s1 = 0;

    #pragma unroll
    for (int it = 0; it < 8; ++it) {
        const int   nb  = it * 4 + grp;
        const int   seg = __shfl_sync(FULLM, b.seg, nb);
        const float inv = __shfl_sync(FULLM, b.inv, nb);
        const bool  act = (nb < cnt);

        float4 wv = b.vv[it];
        wv.x *= inv; wv.y *= inv; wv.z *= inv; wv.w *= inv;

        const unsigned mm     = __match_any_sync(FULLM, seg);
        const bool     leader = (mm & below) == 0u;

        if (!__all_sync(FULLM, leader)) {          // ~9%: donor merge
            const float x1 = __shfl_down_sync(FULLM, wv.x, 8);
            const float y1 = __shfl_down_sync(FULLM, wv.y, 8);
            const float z1 = __shfl_down_sync(FULLM, wv.z, 8);
            const float w1 = __shfl_down_sync(FULLM, wv.w, 8);
            const float x2 = __shfl_down_sync(FULLM, wv.x, 16);
            const float y2 = __shfl_down_sync(FULLM, wv.y, 16);
            const float z2 = __shfl_down_sync(FULLM, wv.z, 16);
            const float w2 = __shfl_down_sync(FULLM, wv.w, 16);
            const float x3 = __shfl_down_sync(FULLM, wv.x, 24);
            const float y3 = __shfl_down_sync(FULLM, wv.y, 24);
            const float z3 = __shfl_down_sync(FULLM, wv.z, 24);
            const float w3 = __shfl_down_sync(FULLM, wv.w, 24);

            const bool c1 = (grp < 3) && ((mm >> ((lane + 8)  & 31)) & 1u);
            const bool c2 = (grp < 2) && ((mm >> ((lane + 16) & 31)) & 1u);
            const bool c3 = (grp < 1) && ((mm >> ((lane + 24) & 31)) & 1u);

            wv.x += (c1 ? x1 : 0.f) + (c2 ? x2 : 0.f) + (c3 ? x3 : 0.f);
            wv.y += (c1 ? y1 : 0.f) + (c2 ? y2 : 0.f) + (c3 ? y3 : 0.f);
            wv.z += (c1 ? z1 : 0.f) + (c2 ? z2 : 0.f) + (c3 ? z3 : 0.f);
            wv.w += (c1 ? w1 : 0.f) + (c2 ? w2 : 0.f) + (c3 ? w3 : 0.f);
        }
        b.vv[it] = wv;

        const unsigned sb = (unsigned)(seg & 63) << ((it & 3) * 8);
        if (it < 4) s0 |= sb; else s1 |= sb;
        if (act && leader) pm |= (1u << it);
    }
    b.sp0 = s0; b.sp1 = s1; b.pmask = pm;
}

__device__ __forceinline__ void rmw_batch(
    float* __restrict__ acc, const Batch& b, int slot)
{
    #pragma unroll
    for (int it = 0; it < 8; ++it) {
        if (b.pmask & (1u << it)) {
            const unsigned sp  = (it < 4) ? b.sp0 : b.sp1;
            const int      seg = (sp >> ((it & 3) * 8)) & 0xFF;
            float4* ap = reinterpret_cast<float4*>(acc + seg * 32 + slot * 4);
            float4 a = *ap;
            const float4 v = b.vv[it];
            a.x += v.x; a.y += v.y; a.z += v.z; a.w += v.w;
            *ap = a;
        }
    }
}

__global__ void __launch_bounds__(128, 5) spp_pipe_kernel(
    const float* __restrict__ feat,
    const int*   __restrict__ xy,
    float*       __restrict__ out,
    int G, int C)
{
    __shared__ float s_acc[4 * 64 * 32];           // 32 KB, stride 32 (no pad)

    const int t    = threadIdx.x;
    const int w    = t >> 5;                       // warp = 32-col slice
    const int lane = t & 31;
    const int grp  = lane >> 3;                    // node group 0..3
    const int slot = lane & 7;                     // float4 slot 0..7
    const unsigned below = grp ? ((1u << (grp * 8)) - 1u) : 0u;

    const int g     = blockIdx.x / C;
    const int chunk = blockIdx.x % C;
    const int gbeg  = g_node_off[g];
    const int glen  = g_node_off[g + 1] - gbeg;
    const int cbeg  = gbeg + (int)((long long)glen * chunk / C);
    const int cend  = gbeg + (int)((long long)glen * (chunk + 1) / C);

    // zero accumulators
    float4* z = reinterpret_cast<float4*>(s_acc);
    #pragma unroll
    for (int i = t; i < 4 * 64 * 8; i += 128) z[i] = make_float4(0.f, 0.f, 0.f, 0.f);
    __syncthreads();

    float* acc = s_acc + w * 64 * 32;
    const float* fbase = feat + (size_t)w * 32 + (size_t)slot * 4;  // ld addr
    const float* fwarp = feat + (size_t)w * 32;                     // pf addr

    // pipeline: load(b+1) + prefetch(b+4) -> rmw(b) -> meta(b+1)   [R9 + pf]
    Batch A, B2;
    int base = cbeg;
    if (base < cend) {
        load_batch(A, xy, fbase, base, cend, G, lane, grp);
        prefetch_batch(fwarp, base + 32, cend, lane);     // warm early batches
        prefetch_batch(fwarp, base + 64, cend, lane);
        prefetch_batch(fwarp, base + 96, cend, lane);
        meta_batch(A, base, cend, lane, grp, below);
        for (;;) {
            const int base2 = base + 32;
            if (base2 < cend) {
                load_batch(B2, xy, fbase, base2, cend, G, lane, grp);
                prefetch_batch(fwarp, base2 + 96, cend, lane);   // b+4
                rmw_batch(acc, A, slot);
                meta_batch(B2, base2, cend, lane, grp, below);
                const int base3 = base2 + 32;
                if (base3 < cend) {
                    load_batch(A, xy, fbase, base3, cend, G, lane, grp);
                    prefetch_batch(fwarp, base3 + 96, cend, lane);  // b+4
                    rmw_batch(acc, B2, slot);
                    meta_batch(A, base3, cend, lane, grp, below);
                    base = base3;
                    continue;
                }
                rmw_batch(acc, B2, slot);
                break;
            }
            rmw_batch(acc, A, slot);
            break;
        }
    }
    __syncwarp();

    // epilogue: each warp flushes its own 8KB slice via RED.v4
    float* dstw = out + (size_t)g * 64 * 128 + (size_t)w * 32;
    #pragma unroll
    for (int i = lane; i < 512; i += 32) {
        const int seg = i >> 3, q = i & 7;
        float4 a = *reinterpret_cast<float4*>(acc + seg * 32 + q * 4);
        asm volatile("red.global.add.v4.f32 [%0], {%1, %2, %3, %4};"
                     :: "l"(dstw + (size_t)seg * 128 + q * 4),
                        "f"(a.x), "f"(a.y), "f"(a.z), "f"(a.w)
                     : "memory");
    }
}

// ---------------- fallback path (round-2 kernel) ----------------
__device__ __forceinline__ int find_graph(const int* s_off, int B, int node) {
    int lo = 0, hi = B;
    while (hi - lo > 1) {
        int mid = (lo + hi) >> 1;
        if (s_off[mid] <= node) lo = mid; else hi = mid;
    }
    return lo;
}

__global__ void __launch_bounds__(256) spp_pool_fallback(
    const float* __restrict__ feat, const int* __restrict__ xy,
    float* __restrict__ out, int N, int D, int G, int B)
{
    extern __shared__ int s_off[];
    for (int i = threadIdx.x; i <= B; i += blockDim.x) s_off[i] = g_node_off[i];
    __syncthreads();

    const int lane   = threadIdx.x & 31;
    const int warp   = (blockIdx.x * blockDim.x + threadIdx.x) >> 5;
    const int nwarps = (gridDim.x * blockDim.x) >> 5;

    for (long long base = (long long)warp * 32; base < N;
         base += (long long)nwarps * 32) {
        long long mynode = base + lane;
        int nd = (mynode < N) ? (int)mynode : (N - 1);
        const int r  = __ldg(&xy[3 * nd + 0]);
        const int c  = __ldg(&xy[3 * nd + 1]);
        const int dv = __ldg(&xy[3 * nd + 2]);
        int gid = find_graph(s_off, B, nd);
        const int   myseg = (gid * G + r) * G + c;
        const float myinv = 1.0f / (float)dv;
        const int cnt = (N - base >= 32) ? 32 : (int)(N - base);

        for (int j = 0; j < cnt; ++j) {
            const int   seg = __shfl_sync(0xffffffffu, myseg, j);
            const float inv = __shfl_sync(0xffffffffu, myinv, j);
            const float* src = feat + ((size_t)(base + j)) * D;
            for (int d4 = lane; d4 * 4 < D; d4 += 32) {
                float4 v = __ldg(reinterpret_cast<const float4*>(src) + d4);
                v.x *= inv; v.y *= inv; v.z *= inv; v.w *= inv;
                float* dst = out + (size_t)seg * D + d4 * 4;
                asm volatile("red.global.add.v4.f32 [%0], {%1, %2, %3, %4};"
                             :: "l"(dst), "f"(v.x), "f"(v.y), "f"(v.z), "f"(v.w)
                             : "memory");
            }
        }
    }
}

extern "C" void kernel_launch(void* const* d_in, const int* in_sizes, int n_in,
                              void* d_out, int out_size) {
    const float* feat = (const float*)d_in[0];
    const int*   xy   = (const int*)d_in[1];
    const int*   bn   = (const int*)d_in[2];
    float*       out  = (float*)d_out;

    const int B = in_sizes[2];
    const int N = in_sizes[1] / 3;
    const int D = in_sizes[0] / N;
    const int S = out_size / D;        // B*G*G
    const int gg = S / B;
    int G = 1;
    while (G * G < gg) ++G;

    k_prefix<<<1, 32>>>(bn, B);

    // output accumulated via RED in both paths -> zero every replay
    cudaMemsetAsync(d_out, 0, (size_t)out_size * sizeof(float), 0);

    const bool fast = (D == 128) && (gg == 64) && (G == 8) &&
                      (S == B * 64) && (B <= 1024);

    if (fast) {
        int C = 704 / B;               // single wave at 5 CTAs/SM (B=64 -> 11)
        if (C < 1) C = 1;
        spp_pipe_kernel<<<B * C, 128>>>(feat, xy, out, G, C);
    } else {
        size_t smem = (size_t)(B + 1) * sizeof(int);
        long long batches = ((long long)N + 31) / 32;
        int blocks = (int)((batches + 7) / 8);
        if (blocks > 65535) blocks = 65535;
        spp_pool_fallback<<<blocks, 256, smem>>>(feat, xy, out, N, D, G, B);
    }
}

// round 17
// speedup vs baseline: 2.0379x; 1.0093x over previous
#include <cuda_runtime.h>
#include <cuda_bf16.h>

// ---------------- static scratch (fallback path only) ----------------
__device__ int g_node_off[1025];

__global__ void k_prefix(const int* __restrict__ bn, int B) {
    if (threadIdx.x == 0) {
        int acc = 0;
        g_node_off[0] = 0;
        for (int i = 0; i < B; ++i) { acc += bn[i]; g_node_off[i + 1] = acc; }
    }
}

// ---------------- fast path (R9 hot loop, self-contained prefix) ------------
// CTA = (graph, chunk); 4 warps, warp w owns 32-col slice [32w, 32w+32).
// Every warp walks all 32-node batches of the chunk.
// Per-warp private accumulator: 64 segs x 32 floats (stride 32, conflict-free).
// Pipeline: load(b+1) -> rmw(b) -> meta(b+1).
// R17: graph offset computed in-CTA (warp-reduce over bn, merged with the
// existing accumulator-zero __syncthreads) -- the separate prefix kernel
// launch is removed from the fast path.
#define FULLM 0xffffffffu

struct Batch {
    int      seg;        // this lane's node seg (64+lane marker if inactive)
    float    inv;
    float4   vv[8];      // after meta: scaled + donor-merged
    unsigned sp0, sp1;   // after meta: segs of iters 0..3 / 4..7, 8b each
    unsigned pmask;      // after meta: bit it = (active && leader)
};

__device__ __forceinline__ void load_batch(
    Batch& b, const int* __restrict__ xy, const float* __restrict__ fbase,
    int base, int cend, int G, int lane, int grp)
{
    const int cnt = cend - base;                   // >= 1 (may exceed 32)
    const int l   = (lane < cnt) ? lane : (cnt - 1);
    const int nd  = base + l;
    const int rr  = __ldg(&xy[3 * nd + 0]);
    const int cc  = __ldg(&xy[3 * nd + 1]);
    const int dv  = __ldg(&xy[3 * nd + 2]);
    b.seg = (lane < cnt) ? (rr * G + cc) : (64 + lane);  // marker never matches
    b.inv = 1.0f / (float)dv;

    #pragma unroll
    for (int it = 0; it < 8; ++it) {
        const int nb   = it * 4 + grp;
        const int node = base + ((nb < cnt) ? nb : (cnt - 1));
        b.vv[it] = __ldg(reinterpret_cast<const float4*>(fbase + (size_t)node * 128));
    }
}

__device__ __forceinline__ void meta_batch(
    Batch& b, int base, int cend, int lane, int grp, unsigned below)
{
    const int cnt = (cend - base >= 32) ? 32 : (cend - base);
    unsigned pm = 0, s0 = 0, s1 = 0;

    #pragma unroll
    for (int it = 0; it < 8; ++it) {
        const int   nb  = it * 4 + grp;
        const int   seg = __shfl_sync(FULLM, b.seg, nb);
        const float inv = __shfl_sync(FULLM, b.inv, nb);
        const bool  act = (nb < cnt);

        float4 wv = b.vv[it];
        wv.x *= inv; wv.y *= inv; wv.z *= inv; wv.w *= inv;

        const unsigned mm     = __match_any_sync(FULLM, seg);
        const bool     leader = (mm & below) == 0u;

        if (!__all_sync(FULLM, leader)) {          // ~9%: donor merge
            const float x1 = __shfl_down_sync(FULLM, wv.x, 8);
            const float y1 = __shfl_down_sync(FULLM, wv.y, 8);
            const float z1 = __shfl_down_sync(FULLM, wv.z, 8);
            const float w1 = __shfl_down_sync(FULLM, wv.w, 8);
            const float x2 = __shfl_down_sync(FULLM, wv.x, 16);
            const float y2 = __shfl_down_sync(FULLM, wv.y, 16);
            const float z2 = __shfl_down_sync(FULLM, wv.z, 16);
            const float w2 = __shfl_down_sync(FULLM, wv.w, 16);
            const float x3 = __shfl_down_sync(FULLM, wv.x, 24);
            const float y3 = __shfl_down_sync(FULLM, wv.y, 24);
            const float z3 = __shfl_down_sync(FULLM, wv.z, 24);
            const float w3 = __shfl_down_sync(FULLM, wv.w, 24);

            const bool c1 = (grp < 3) && ((mm >> ((lane + 8)  & 31)) & 1u);
            const bool c2 = (grp < 2) && ((mm >> ((lane + 16) & 31)) & 1u);
            const bool c3 = (grp < 1) && ((mm >> ((lane + 24) & 31)) & 1u);

            wv.x += (c1 ? x1 : 0.f) + (c2 ? x2 : 0.f) + (c3 ? x3 : 0.f);
            wv.y += (c1 ? y1 : 0.f) + (c2 ? y2 : 0.f) + (c3 ? y3 : 0.f);
            wv.z += (c1 ? z1 : 0.f) + (c2 ? z2 : 0.f) + (c3 ? z3 : 0.f);
            wv.w += (c1 ? w1 : 0.f) + (c2 ? w2 : 0.f) + (c3 ? w3 : 0.f);
        }
        b.vv[it] = wv;

        const unsigned sb = (unsigned)(seg & 63) << ((it & 3) * 8);
        if (it < 4) s0 |= sb; else s1 |= sb;
        if (act && leader) pm |= (1u << it);
    }
    b.sp0 = s0; b.sp1 = s1; b.pmask = pm;
}

__device__ __forceinline__ void rmw_batch(
    float* __restrict__ acc, const Batch& b, int slot)
{
    #pragma unroll
    for (int it = 0; it < 8; ++it) {
        if (b.pmask & (1u << it)) {
            const unsigned sp  = (it < 4) ? b.sp0 : b.sp1;
            const int      seg = (sp >> ((it & 3) * 8)) & 0xFF;
            float4* ap = reinterpret_cast<float4*>(acc + seg * 32 + slot * 4);
            float4 a = *ap;
            const float4 v = b.vv[it];
            a.x += v.x; a.y += v.y; a.z += v.z; a.w += v.w;
            *ap = a;
        }
    }
}

__global__ void __launch_bounds__(128, 5) spp_pipe_kernel(
    const float* __restrict__ feat,
    const int*   __restrict__ xy,
    const int*   __restrict__ bn,
    float*       __restrict__ out,
    int G, int C)
{
    __shared__ float s_acc[4 * 64 * 32];           // 32 KB, stride 32 (no pad)
    __shared__ int   s_range[2];                   // gbeg, gend

    const int t    = threadIdx.x;
    const int w    = t >> 5;                       // warp = 32-col slice
    const int lane = t & 31;
    const int grp  = lane >> 3;                    // node group 0..3
    const int slot = lane & 7;                     // float4 slot 0..7
    const unsigned below = grp ? ((1u << (grp * 8)) - 1u) : 0u;

    const int g     = blockIdx.x / C;
    const int chunk = blockIdx.x % C;

    // in-CTA prefix: gbeg = sum(bn[0..g)), gend = gbeg + bn[g]  (warp 0)
    if (w == 0) {
        int s = 0;
        for (int i = lane; i < g; i += 32) s += __ldg(&bn[i]);
        #pragma unroll
        for (int o = 16; o > 0; o >>= 1) s += __shfl_down_sync(FULLM, s, o);
        if (lane == 0) {
            s_range[0] = s;
            s_range[1] = s + __ldg(&bn[g]);
        }
    }

    // zero accumulators
    float4* z = reinterpret_cast<float4*>(s_acc);
    #pragma unroll
    for (int i = t; i < 4 * 64 * 8; i += 128) z[i] = make_float4(0.f, 0.f, 0.f, 0.f);
    __syncthreads();                               // covers s_range + s_acc

    const int gbeg = s_range[0];
    const int glen = s_range[1] - gbeg;
    const int cbeg = gbeg + (int)((long long)glen * chunk / C);
    const int cend = gbeg + (int)((long long)glen * (chunk + 1) / C);

    float* acc = s_acc + w * 64 * 32;
    const float* fbase = feat + (size_t)w * 32 + (size_t)slot * 4;

    // pipeline: load(b+1) -> rmw(b) -> meta(b+1)
    Batch A, B2;
    int base = cbeg;
    if (base < cend) {
        load_batch(A, xy, fbase, base, cend, G, lane, grp);
        meta_batch(A, base, cend, lane, grp, below);
        for (;;) {
            const int base2 = base + 32;
            if (base2 < cend) {
                load_batch(B2, xy, fbase, base2, cend, G, lane, grp);
                rmw_batch(acc, A, slot);
                meta_batch(B2, base2, cend, lane, grp, below);
                const int base3 = base2 + 32;
                if (base3 < cend) {
                    load_batch(A, xy, fbase, base3, cend, G, lane, grp);
                    rmw_batch(acc, B2, slot);
                    meta_batch(A, base3, cend, lane, grp, below);
                    base = base3;
                    continue;
                }
                rmw_batch(acc, B2, slot);
                break;
            }
            rmw_batch(acc, A, slot);
            break;
        }
    }
    __syncwarp();

    // epilogue: each warp flushes its own 8KB slice via RED.v4
    float* dstw = out + (size_t)g * 64 * 128 + (size_t)w * 32;
    #pragma unroll
    for (int i = lane; i < 512; i += 32) {
        const int seg = i >> 3, q = i & 7;
        float4 a = *reinterpret_cast<float4*>(acc + seg * 32 + q * 4);
        asm volatile("red.global.add.v4.f32 [%0], {%1, %2, %3, %4};"
                     :: "l"(dstw + (size_t)seg * 128 + q * 4),
                        "f"(a.x), "f"(a.y), "f"(a.z), "f"(a.w)
                     : "memory");
    }
}

// ---------------- fallback path (round-2 kernel) ----------------
__device__ __forceinline__ int find_graph(const int* s_off, int B, int node) {
    int lo = 0, hi = B;
    while (hi - lo > 1) {
        int mid = (lo + hi) >> 1;
        if (s_off[mid] <= node) lo = mid; else hi = mid;
    }
    return lo;
}

__global__ void __launch_bounds__(256) spp_pool_fallback(
    const float* __restrict__ feat, const int* __restrict__ xy,
    float* __restrict__ out, int N, int D, int G, int B)
{
    extern __shared__ int s_off[];
    for (int i = threadIdx.x; i <= B; i += blockDim.x) s_off[i] = g_node_off[i];
    __syncthreads();

    const int lane   = threadIdx.x & 31;
    const int warp   = (blockIdx.x * blockDim.x + threadIdx.x) >> 5;
    const int nwarps = (gridDim.x * blockDim.x) >> 5;

    for (long long base = (long long)warp * 32; base < N;
         base += (long long)nwarps * 32) {
        long long mynode = base + lane;
        int nd = (mynode < N) ? (int)mynode : (N - 1);
        const int r  = __ldg(&xy[3 * nd + 0]);
        const int c  = __ldg(&xy[3 * nd + 1]);
        const int dv = __ldg(&xy[3 * nd + 2]);
        int gid = find_graph(s_off, B, nd);
        const int   myseg = (gid * G + r) * G + c;
        const float myinv = 1.0f / (float)dv;
        const int cnt = (N - base >= 32) ? 32 : (int)(N - base);

        for (int j = 0; j < cnt; ++j) {
            const int   seg = __shfl_sync(0xffffffffu, myseg, j);
            const float inv = __shfl_sync(0xffffffffu, myinv, j);
            const float* src = feat + ((size_t)(base + j)) * D;
            for (int d4 = lane; d4 * 4 < D; d4 += 32) {
                float4 v = __ldg(reinterpret_cast<const float4*>(src) + d4);
                v.x *= inv; v.y *= inv; v.z *= inv; v.w *= inv;
                float* dst = out + (size_t)seg * D + d4 * 4;
                asm volatile("red.global.add.v4.f32 [%0], {%1, %2, %3, %4};"
                             :: "l"(dst), "f"(v.x), "f"(v.y), "f"(v.z), "f"(v.w)
                             : "memory");
            }
        }
    }
}

extern "C" void kernel_launch(void* const* d_in, const int* in_sizes, int n_in,
                              void* d_out, int out_size) {
    const float* feat = (const float*)d_in[0];
    const int*   xy   = (const int*)d_in[1];
    const int*   bn   = (const int*)d_in[2];
    float*       out  = (float*)d_out;

    const int B = in_sizes[2];
    const int N = in_sizes[1] / 3;
    const int D = in_sizes[0] / N;
    const int S = out_size / D;        // B*G*G
    const int gg = S / B;
    int G = 1;
    while (G * G < gg) ++G;

    // output accumulated via RED in both paths -> zero every replay
    cudaMemsetAsync(d_out, 0, (size_t)out_size * sizeof(float), 0);

    const bool fast = (D == 128) && (gg == 64) && (G == 8) &&
                      (S == B * 64) && (B <= 1024);

    if (fast) {
        int C = 704 / B;               // single wave at 5 CTAs/SM (B=64 -> 11)
        if (C < 1) C = 1;
        spp_pipe_kernel<<<B * C, 128>>>(feat, xy, bn, out, G, C);
    } else {
        k_prefix<<<1, 32>>>(bn, B);
        size_t smem = (size_t)(B + 1) * sizeof(int);
        long long batches = ((long long)N + 31) / 32;
        int blocks = (int)((batches + 7) / 8);
        if (blocks > 65535) blocks = 65535;
        spp_pool_fallback<<<blocks, 256, smem>>>(feat, xy, out, N, D, G, B);
    }
}